// round 14
// baseline (speedup 1.0000x reference)
#include <cuda_runtime.h>
#include <cuda_fp16.h>
#include <math.h>

#define NMAX 50000
#define EMAX 800000
#define HDIM 64

// ---------------- scratch (static __device__, no allocation) ----------------
__device__ float  g_hyp[NMAX * HDIM];
__device__ float  g_h0 [NMAX * HDIM];
__device__ float  g_h1 [NMAX * HDIM];
__device__ __half g_yh [NMAX * HDIM];
__device__ float  g_z  [NMAX * HDIM];
__device__ int    g_rowptr[NMAX + 1];
__device__ int    g_cnt[NMAX];
__device__ int    g_epos[EMAX];
__device__ int    g_adj[EMAX];

// ---------------- CSR build ----------------
__global__ void count_kernel(const int* __restrict__ dst, int* cnt, int* pos, int E) {
    int e = blockIdx.x * blockDim.x + threadIdx.x;
    if (e < E) pos[e] = atomicAdd(&cnt[dst[e]], 1);
}

__global__ void scan_kernel(const int* __restrict__ cnt, int* rowptr, int N) {
    __shared__ int s[1024];
    int t = threadIdx.x;
    int chunk = (N + 1023) / 1024;
    int beg = t * chunk;
    int end = min(beg + chunk, N);
    int sum = 0;
    for (int i = beg; i < end; i++) sum += cnt[i];
    s[t] = sum;
    __syncthreads();
    for (int off = 1; off < 1024; off <<= 1) {
        int v = (t >= off) ? s[t - off] : 0;
        __syncthreads();
        s[t] += v;
        __syncthreads();
    }
    int run = s[t] - sum;
    for (int i = beg; i < end; i++) { rowptr[i] = run; run += cnt[i]; }
    if (end == N) rowptr[N] = run;
}

__global__ void fill_kernel(const int* __restrict__ src, const int* __restrict__ dst,
                            const int* __restrict__ rowptr, const int* __restrict__ pos,
                            int* adj, int E) {
    int e = blockIdx.x * blockDim.x + threadIdx.x;
    if (e < E) adj[rowptr[dst[e]] + pos[e]] = src[e];
}

// ---- fused layer 0: h0 = X@Wi + bi (SMEM only), then Yh = h0@Wl ; Z = h0@Wr + b
// X:[N,128]. Block: 64 nodes, 256 threads. NO hyp here (added in agg0).
__global__ __launch_bounds__(256, 2)
void init_dual(const float* __restrict__ X, const float* __restrict__ Wi,
               const float* __restrict__ bi,
               const float* __restrict__ Wl, const float* __restrict__ Wr,
               const float* __restrict__ bias,
               __half* __restrict__ Yh, float* __restrict__ Z, int N) {
    __shared__ float Xs[128 * 68];   // [k][node] transposed x tile
    __shared__ float Hs[64 * 68];    // [node][k] h0 tile
    __shared__ float Ws[64 * 128];   // dual weights [k][j], j<64 Wl, j>=64 Wr
    const int node0 = blockIdx.x * 64;
    const int tid = threadIdx.x;

    // stage dual Ws: 2048 float4 / 256 thr = 8 each
    {
        const float4* Wl4 = (const float4*)Wl;
        const float4* Wr4 = (const float4*)Wr;
        float4* Ws4 = (float4*)Ws;
#pragma unroll
        for (int r = 0; r < 8; r++) {
            int idx = r * 256 + tid;
            int k = idx >> 5, j4 = idx & 31;
            Ws4[idx] = (j4 < 16) ? __ldg(&Wl4[k * 16 + j4])
                                 : __ldg(&Wr4[k * 16 + (j4 - 16)]);
        }
    }
    // stage Xs (transposed): 8192 scalars / 256 thr = 32 each, coalesced gmem
    for (int i = tid; i < 64 * 128; i += 256) {
        int nl = i >> 7, k = i & 127;
        int n = node0 + nl;
        Xs[k * 68 + nl] = (n < N) ? __ldg(&X[(size_t)n * 128 + k]) : 0.f;
    }
    __syncthreads();

    // phase 1: h0 tile -> Hs  (fr: 4 feats, nr: 4 nodes)
    {
        const int fr = tid & 15;
        const int nr = tid >> 4;
        float acc[4][4];
#pragma unroll
        for (int i = 0; i < 4; i++)
#pragma unroll
            for (int j = 0; j < 4; j++) acc[i][j] = 0.f;

#pragma unroll 4
        for (int k = 0; k < 128; k++) {
            float4 av = *(const float4*)&Xs[k * 68 + nr * 4];
            float4 wv = __ldg((const float4*)&Wi[(size_t)k * 64 + fr * 4]);
            float a[4] = {av.x, av.y, av.z, av.w};
            float w[4] = {wv.x, wv.y, wv.z, wv.w};
#pragma unroll
            for (int i = 0; i < 4; i++)
#pragma unroll
                for (int j = 0; j < 4; j++) acc[i][j] += a[i] * w[j];
        }
        float4 b4 = __ldg((const float4*)&bi[fr * 4]);
#pragma unroll
        for (int i = 0; i < 4; i++) {
            float4 v = make_float4(acc[i][0] + b4.x, acc[i][1] + b4.y,
                                   acc[i][2] + b4.z, acc[i][3] + b4.w);
            *(float4*)&Hs[(nr * 4 + i) * 68 + fr * 4] = v;
        }
    }
    __syncthreads();

    // phase 2: dual GEMM from Hs (fr2: 4 of 128 outs, nr2: 8 nodes)
    const int fr2 = tid & 31;
    const int nr2 = tid >> 5;
    const int j0 = fr2 * 4;
    float acc[8][4];
#pragma unroll
    for (int i = 0; i < 8; i++)
#pragma unroll
        for (int j = 0; j < 4; j++) acc[i][j] = 0.f;

    const float* hsb = &Hs[nr2 * 8 * 68];
#pragma unroll 4
    for (int k = 0; k < 64; k++) {
        float4 wv = *(const float4*)&Ws[k * 128 + j0];
        float w[4] = {wv.x, wv.y, wv.z, wv.w};
        float a[8];
#pragma unroll
        for (int i = 0; i < 8; i++) a[i] = hsb[i * 68 + k];
#pragma unroll
        for (int i = 0; i < 8; i++)
#pragma unroll
            for (int j = 0; j < 4; j++) acc[i][j] += a[i] * w[j];
    }

    if (j0 < 64) {
#pragma unroll
        for (int i = 0; i < 8; i++) {
            int n = node0 + nr2 * 8 + i;
            if (n >= N) break;
            __half2 p[2];
            p[0] = __floats2half2_rn(acc[i][0], acc[i][1]);
            p[1] = __floats2half2_rn(acc[i][2], acc[i][3]);
            *(uint2*)&Yh[(size_t)n * 64 + j0] = *(const uint2*)p;
        }
    } else {
        int f0 = j0 - 64;
        float4 b4 = __ldg((const float4*)&bias[f0]);
#pragma unroll
        for (int i = 0; i < 8; i++) {
            int n = node0 + nr2 * 8 + i;
            if (n >= N) break;
            *(float4*)&Z[(size_t)n * 64 + f0] =
                make_float4(acc[i][0] + b4.x, acc[i][1] + b4.y,
                            acc[i][2] + b4.z, acc[i][3] + b4.w);
        }
    }
}

// ------------- dual GEMM: Yh(half) = A@Wl ; Z = A@Wr + b (+hyp) -------------
// A:[N,64], Wl/Wr:[64,64] row-major. Block: 64 nodes x 128 outputs, 128 thr.
__global__ __launch_bounds__(128, 4)
void gemm_dual(const float* __restrict__ A,
               const float* __restrict__ Wl, const float* __restrict__ Wr,
               const float* __restrict__ bias, const float* __restrict__ hyp,
               __half* __restrict__ Yh, float* __restrict__ Z, int N) {
    __shared__ float As[64 * 65];
    __shared__ float Ws[64 * 128];
    const int node0 = blockIdx.x * 64;
    const int tid = threadIdx.x;

    {
        const float4* Wl4 = (const float4*)Wl;
        const float4* Wr4 = (const float4*)Wr;
        float4* Ws4 = (float4*)Ws;
#pragma unroll
        for (int r = 0; r < 16; r++) {
            int idx = r * 128 + tid;
            int k = idx >> 5, j4 = idx & 31;
            Ws4[idx] = (j4 < 16) ? __ldg(&Wl4[k * 16 + j4])
                                 : __ldg(&Wr4[k * 16 + (j4 - 16)]);
        }
    }
    {
#pragma unroll
        for (int r = 0; r < 8; r++) {
            int idx = r * 128 + tid;
            int nl = idx >> 4, c4 = idx & 15;
            int n = node0 + nl;
            float4 v = make_float4(0.f, 0.f, 0.f, 0.f);
            if (n < N) v = __ldg((const float4*)(A + (size_t)n * 64) + c4);
            float* d = &As[nl * 65 + c4 * 4];
            d[0] = v.x; d[1] = v.y; d[2] = v.z; d[3] = v.w;
        }
    }
    __syncthreads();

    const int fr = tid & 15;
    const int nr = tid >> 4;
    float acc[8][8];
#pragma unroll
    for (int i = 0; i < 8; i++)
#pragma unroll
        for (int j = 0; j < 8; j++) acc[i][j] = 0.f;

    const float* asb = &As[nr * 8 * 65];
#pragma unroll 4
    for (int k = 0; k < 64; k++) {
        float4 w0 = *(const float4*)&Ws[k * 128 + fr * 8];
        float4 w1 = *(const float4*)&Ws[k * 128 + fr * 8 + 4];
        float w[8] = {w0.x, w0.y, w0.z, w0.w, w1.x, w1.y, w1.z, w1.w};
        float a[8];
#pragma unroll
        for (int i = 0; i < 8; i++) a[i] = asb[i * 65 + k];
#pragma unroll
        for (int i = 0; i < 8; i++)
#pragma unroll
            for (int j = 0; j < 8; j++) acc[i][j] += a[i] * w[j];
    }

    if (fr < 8) {
        int f0 = fr * 8;
#pragma unroll
        for (int i = 0; i < 8; i++) {
            int n = node0 + nr * 8 + i;
            if (n >= N) break;
            __half2 p[4];
#pragma unroll
            for (int j = 0; j < 4; j++)
                p[j] = __floats2half2_rn(acc[i][2 * j], acc[i][2 * j + 1]);
            *(uint4*)&Yh[(size_t)n * 64 + f0] = *(const uint4*)p;
        }
    } else {
        int f0 = (fr - 8) * 8;
        float b[8];
#pragma unroll
        for (int j = 0; j < 8; j++) b[j] = __ldg(&bias[f0 + j]);
#pragma unroll
        for (int i = 0; i < 8; i++) {
            int n = node0 + nr * 8 + i;
            if (n >= N) break;
            float v[8];
#pragma unroll
            for (int j = 0; j < 8; j++) v[j] = acc[i][j] + b[j];
            if (hyp) {
                float4 h0v = __ldg((const float4*)&hyp[(size_t)n * 64 + f0]);
                float4 h1v = __ldg((const float4*)&hyp[(size_t)n * 64 + f0 + 4]);
                v[0] += h0v.x; v[1] += h0v.y; v[2] += h0v.z; v[3] += h0v.w;
                v[4] += h1v.x; v[5] += h1v.y; v[6] += h1v.z; v[7] += h1v.w;
            }
            *(float4*)&Z[(size_t)n * 64 + f0]     = make_float4(v[0], v[1], v[2], v[3]);
            *(float4*)&Z[(size_t)n * 64 + f0 + 4] = make_float4(v[4], v[5], v[6], v[7]);
        }
    }
}

// ------- fused gather-mean + Z (+hyp) + act: out = act(mean(Yh[src]) + Z [+hyp])
__global__ void agg_epi(const __half* __restrict__ Yh, const float* __restrict__ Z,
                        const float* __restrict__ hyp, float* __restrict__ out,
                        const int* __restrict__ rowptr, const int* __restrict__ adj,
                        int N, int relu) {
    int gw = (blockIdx.x * blockDim.x + threadIdx.x) >> 5;
    int lane = threadIdx.x & 31;
    if (gw >= N) return;
    int beg = rowptr[gw];
    int end = rowptr[gw + 1];
    float ax = 0.f, ay = 0.f;
#pragma unroll 4
    for (int e = beg; e < end; e++) {
        int s = __ldg(&adj[e]);
        __half2 hv = __ldg(((const __half2*)(Yh + (size_t)s * HDIM)) + lane);
        float2 v = __half22float2(hv);
        ax += v.x; ay += v.y;
    }
    float inv = 1.f / (float)max(end - beg, 1);
    float2 z = __ldg(((const float2*)(Z + (size_t)gw * HDIM)) + lane);
    float ox = ax * inv + z.x;
    float oy = ay * inv + z.y;
    if (hyp) {
        float2 hv = __ldg(((const float2*)(hyp + (size_t)gw * HDIM)) + lane);
        ox += hv.x; oy += hv.y;
    }
    if (relu) { ox = fmaxf(ox, 0.f); oy = fmaxf(oy, 0.f); }
    ((float2*)(out + (size_t)gw * HDIM))[lane] = make_float2(ox, oy);
}

// ---------------- pos: out = tanh(pos @ W_pos + b), warp-per-node -----------
__global__ __launch_bounds__(256)
void pos_kernel(const float* __restrict__ pos, const float* __restrict__ W,
                const float* __restrict__ b, float* __restrict__ out, int N) {
    __shared__ float Ws[16 * 64];
    __shared__ float bs[64];
    int tid = threadIdx.x;
    for (int i = tid; i < 16 * 64; i += 256) Ws[i] = W[i];
    if (tid < 64) bs[tid] = b[tid];
    __syncthreads();

    int warp = tid >> 5, lane = tid & 31;
    int n = blockIdx.x * 8 + warp;
    if (n >= N) return;

    float pval = (lane < 16) ? __ldg(&pos[(size_t)n * 16 + lane]) : 0.f;
    int j0 = lane * 2;
    float a0 = bs[j0], a1 = bs[j0 + 1];
#pragma unroll
    for (int k = 0; k < 16; k++) {
        float pv = __shfl_sync(0xffffffffu, pval, k);
        float2 w = *(const float2*)&Ws[k * 64 + j0];
        a0 += pv * w.x; a1 += pv * w.y;
    }
    ((float2*)(out + (size_t)n * 64))[lane] = make_float2(tanhf(a0), tanhf(a1));
}

// ---------------- final: emb = h@W_last + b; log_softmax -----------------
__global__ void final_kernel(const float* __restrict__ h, const float* __restrict__ W,
                             const float* __restrict__ b, float* __restrict__ out,
                             int N, int out_size) {
    __shared__ float Ws[64 * 40];
    __shared__ float bs[40];
    int tid = threadIdx.x;
    for (int i = tid; i < 64 * 40; i += 256) Ws[i] = W[i];
    if (tid < 40) bs[tid] = b[tid];
    __syncthreads();

    int n = blockIdx.x * 256 + tid;
    if (n >= N) return;

    float acc[40];
#pragma unroll
    for (int c = 0; c < 40; c++) acc[c] = bs[c];
    const float* hr = h + (size_t)n * 64;
#pragma unroll 4
    for (int k = 0; k < 64; k++) {
        float hv = __ldg(&hr[k]);
#pragma unroll
        for (int c = 0; c < 40; c++) acc[c] += hv * Ws[k * 40 + c];
    }
    float mx = acc[0];
#pragma unroll
    for (int c = 1; c < 40; c++) mx = fmaxf(mx, acc[c]);
    float sum = 0.f;
#pragma unroll
    for (int c = 0; c < 40; c++) sum += expf(acc[c] - mx);
    float lse = mx + logf(sum);

    size_t base = (size_t)n * 40;
    size_t base2 = (size_t)N * 40 + base;
#pragma unroll
    for (int c = 0; c < 40; c++) {
        if (base + c < (size_t)out_size) out[base + c] = acc[c];
        if (base2 + c < (size_t)out_size) out[base2 + c] = acc[c] - lse;
    }
}

// ---------------- launch ----------------
extern "C" void kernel_launch(void* const* d_in, const int* in_sizes, int n_in,
                              void* d_out, int out_size) {
    const float* x_h    = (const float*)d_in[0];
    const float* pos    = (const float*)d_in[1];
    const int*   ei     = (const int*)  d_in[2];
    const float* W_pos  = (const float*)d_in[3];
    const float* b_pos  = (const float*)d_in[4];
    const float* W_init = (const float*)d_in[5];
    const float* b_init = (const float*)d_in[6];
    const float* W_l    = (const float*)d_in[7];
    const float* W_r    = (const float*)d_in[8];
    const float* b_conv = (const float*)d_in[9];
    const float* W_last = (const float*)d_in[10];
    const float* b_last = (const float*)d_in[11];

    int N = in_sizes[0] / 128;
    int E = in_sizes[2] / 2;

    float *hyp, *h0, *h1, *zbuf;
    __half* ybuf;
    int *rowptr, *cnt, *epos, *adj;
    cudaGetSymbolAddress((void**)&hyp,    g_hyp);
    cudaGetSymbolAddress((void**)&h0,     g_h0);
    cudaGetSymbolAddress((void**)&h1,     g_h1);
    cudaGetSymbolAddress((void**)&ybuf,   g_yh);
    cudaGetSymbolAddress((void**)&zbuf,   g_z);
    cudaGetSymbolAddress((void**)&rowptr, g_rowptr);
    cudaGetSymbolAddress((void**)&cnt,    g_cnt);
    cudaGetSymbolAddress((void**)&epos,   g_epos);
    cudaGetSymbolAddress((void**)&adj,    g_adj);

    const int* src = ei;
    const int* dst = ei + E;

    static cudaStream_t s1 = nullptr, s2 = nullptr;
    static cudaEvent_t ev_fork = nullptr, ev_pos = nullptr, ev_join = nullptr;
    if (!s1) {
        cudaStreamCreateWithFlags(&s1, cudaStreamNonBlocking);
        cudaStreamCreateWithFlags(&s2, cudaStreamNonBlocking);
        cudaEventCreateWithFlags(&ev_fork, cudaEventDisableTiming);
        cudaEventCreateWithFlags(&ev_pos,  cudaEventDisableTiming);
        cudaEventCreateWithFlags(&ev_join, cudaEventDisableTiming);
    }

    // ---- fork: CSR on s1, pos on s2, fused dense pipeline on main ----
    cudaEventRecord(ev_fork, 0);
    cudaStreamWaitEvent(s1, ev_fork, 0);
    cudaStreamWaitEvent(s2, ev_fork, 0);

    cudaMemsetAsync(cnt, 0, (size_t)NMAX * sizeof(int), s1);
    count_kernel<<<(E + 255) / 256, 256, 0, s1>>>(dst, cnt, epos, E);
    scan_kernel <<<1, 1024, 0, s1>>>(cnt, rowptr, N);
    fill_kernel <<<(E + 255) / 256, 256, 0, s1>>>(src, dst, rowptr, epos, adj, E);
    cudaEventRecord(ev_join, s1);

    pos_kernel<<<(N + 7) / 8, 256, 0, s2>>>(pos, W_pos, b_pos, hyp, N);
    cudaEventRecord(ev_pos, s2);

    int gb64 = (N + 63) / 64;
    // fused layer 0: h0 (SMEM) -> Y,Z. No hyp dependency -> starts immediately.
    init_dual<<<gb64, 256>>>(x_h, W_init, b_init, W_l, W_r, b_conv, ybuf, zbuf, N);

    // ---- join: CSR + hyp must be ready before first aggregation ----
    cudaStreamWaitEvent(0, ev_join, 0);
    cudaStreamWaitEvent(0, ev_pos, 0);

    // agg0 adds hyp (moved out of layer-0 epilogue) + relu
    agg_epi<<<(N + 7) / 8, 256>>>(ybuf, zbuf, hyp, h1, rowptr, adj, N, 1);

    float* hc = h1;
    float* hn = h0;
    for (int l = 1; l < 3; l++) {
        const float* Wl = W_l + (size_t)l * 64 * 64;
        const float* Wr = W_r + (size_t)l * 64 * 64;
        const float* bc = b_conv + (size_t)l * 64;
        const float* av = (l < 2) ? hyp : nullptr;
        int act = (l < 2) ? 1 : 0;
        gemm_dual<<<gb64, 128>>>(hc, Wl, Wr, bc, av, ybuf, zbuf, N);
        agg_epi<<<(N + 7) / 8, 256>>>(ybuf, zbuf, nullptr, hn, rowptr, adj, N, act);
        float* t = hc; hc = hn; hn = t;
    }

    final_kernel<<<(N + 255) / 256, 256>>>(hc, W_last, b_last, (float*)d_out, N, out_size);
}

// round 17
// speedup vs baseline: 1.2699x; 1.2699x over previous
#include <cuda_runtime.h>
#include <cuda_fp16.h>
#include <math.h>

#define NMAX 50000
#define EMAX 800000
#define HDIM 64

// ---------------- scratch (static __device__, no allocation) ----------------
__device__ float  g_hyp[NMAX * HDIM];
__device__ float  g_h0 [NMAX * HDIM];
__device__ float  g_h1 [NMAX * HDIM];
__device__ __half g_yh [NMAX * HDIM];
__device__ float  g_z  [NMAX * HDIM];
__device__ int    g_rowptr[NMAX + 1];
__device__ int    g_cnt[NMAX];
__device__ int    g_epos[EMAX];
__device__ int    g_adj[EMAX];

// ---------------- CSR build ----------------
__global__ void count_kernel(const int* __restrict__ dst, int* cnt, int* pos, int E) {
    int e = blockIdx.x * blockDim.x + threadIdx.x;
    if (e < E) pos[e] = atomicAdd(&cnt[dst[e]], 1);
}

// single-block exclusive scan: 1024 threads, sequential chunks + Hillis-Steele
__global__ void scan_kernel(const int* __restrict__ cnt, int* rowptr, int N) {
    __shared__ int s[1024];
    int t = threadIdx.x;
    int chunk = (N + 1023) / 1024;
    int beg = t * chunk;
    int end = min(beg + chunk, N);
    int sum = 0;
    for (int i = beg; i < end; i++) sum += cnt[i];
    s[t] = sum;
    __syncthreads();
    for (int off = 1; off < 1024; off <<= 1) {
        int v = (t >= off) ? s[t - off] : 0;
        __syncthreads();
        s[t] += v;
        __syncthreads();
    }
    int run = s[t] - sum;
    for (int i = beg; i < end; i++) { rowptr[i] = run; run += cnt[i]; }
    if (end == N) rowptr[N] = run;
}

__global__ void fill_kernel(const int* __restrict__ src, const int* __restrict__ dst,
                            const int* __restrict__ rowptr, const int* __restrict__ pos,
                            int* adj, int E) {
    int e = blockIdx.x * blockDim.x + threadIdx.x;
    if (e < E) adj[rowptr[dst[e]] + pos[e]] = src[e];
}

// --- split dual GEMM: blockIdx.y==0: Yh = A@Wl (fp16); ==1: Z = A@Wr + b (+hyp)
// A:[N,64], W:[64,64] row-major. Block: 64 nodes x 64 outs, 128 threads.
__global__ __launch_bounds__(128, 6)
void gemm_dual_split(const float* __restrict__ A,
                     const float* __restrict__ Wl, const float* __restrict__ Wr,
                     const float* __restrict__ bias, const float* __restrict__ hyp,
                     __half* __restrict__ Yh, float* __restrict__ Z, int N) {
    __shared__ float As[64 * 65];   // [node][k], pad 65 (conflict-free k reads)
    __shared__ float Ws[64 * 64];   // [k][j], one matrix (stride 64 -> LDS.128 ok)
    const int node0 = blockIdx.x * 64;
    const int sel = blockIdx.y;     // 0 = Y(Wl), 1 = Z(Wr)
    const int tid = threadIdx.x;

    // stage Ws: 1024 float4 / 128 threads = 8 each (coalesced)
    {
        const float4* W4 = (const float4*)(sel ? Wr : Wl);
        float4* Ws4 = (float4*)Ws;
#pragma unroll
        for (int r = 0; r < 8; r++) {
            int idx = r * 128 + tid;
            Ws4[idx] = __ldg(&W4[idx]);
        }
    }
    // stage As: 64 nodes x 16 float4 = 1024 f4 / 128 threads = 8 each
    {
#pragma unroll
        for (int r = 0; r < 8; r++) {
            int idx = r * 128 + tid;
            int nl = idx >> 4, c4 = idx & 15;
            int n = node0 + nl;
            float4 v = make_float4(0.f, 0.f, 0.f, 0.f);
            if (n < N) v = __ldg((const float4*)(A + (size_t)n * 64) + c4);
            float* d = &As[nl * 65 + c4 * 4];
            d[0] = v.x; d[1] = v.y; d[2] = v.z; d[3] = v.w;
        }
    }
    __syncthreads();

    const int fr = tid & 15;   // 4 feats fr*4..+3 (of 64)
    const int nr = tid >> 4;   // 8 nodes nr*8..+7 (of 64)
    const int j0 = fr * 4;
    float acc[8][4];
#pragma unroll
    for (int i = 0; i < 8; i++)
#pragma unroll
        for (int j = 0; j < 4; j++) acc[i][j] = 0.f;

    const float* asb = &As[nr * 8 * 65];
#pragma unroll 4
    for (int k = 0; k < 64; k++) {
        float4 wv = *(const float4*)&Ws[k * 64 + j0];
        float w[4] = {wv.x, wv.y, wv.z, wv.w};
        float a[8];
#pragma unroll
        for (int i = 0; i < 8; i++) a[i] = asb[i * 65 + k];
#pragma unroll
        for (int i = 0; i < 8; i++)
#pragma unroll
            for (int j = 0; j < 4; j++) acc[i][j] += a[i] * w[j];
    }

    if (sel == 0) {
        // Y: write fp16 (2 x half2 = 8B)
#pragma unroll
        for (int i = 0; i < 8; i++) {
            int n = node0 + nr * 8 + i;
            if (n >= N) break;
            __half2 p[2];
            p[0] = __floats2half2_rn(acc[i][0], acc[i][1]);
            p[1] = __floats2half2_rn(acc[i][2], acc[i][3]);
            *(uint2*)&Yh[(size_t)n * 64 + j0] = *(const uint2*)p;
        }
    } else {
        float4 b4 = __ldg((const float4*)&bias[j0]);
#pragma unroll
        for (int i = 0; i < 8; i++) {
            int n = node0 + nr * 8 + i;
            if (n >= N) break;
            float4 v = make_float4(acc[i][0] + b4.x, acc[i][1] + b4.y,
                                   acc[i][2] + b4.z, acc[i][3] + b4.w);
            if (hyp) {
                float4 hv = __ldg((const float4*)&hyp[(size_t)n * 64 + j0]);
                v.x += hv.x; v.y += hv.y; v.z += hv.z; v.w += hv.w;
            }
            *(float4*)&Z[(size_t)n * 64 + j0] = v;
        }
    }
}

// ------------- fused gather-mean + Z + act: out = act(mean(Yh[src]) + Z) ----
__global__ void agg_epi(const __half* __restrict__ Yh, const float* __restrict__ Z,
                        float* __restrict__ out,
                        const int* __restrict__ rowptr, const int* __restrict__ adj,
                        int N, int relu) {
    int gw = (blockIdx.x * blockDim.x + threadIdx.x) >> 5;
    int lane = threadIdx.x & 31;
    if (gw >= N) return;
    int beg = rowptr[gw];
    int end = rowptr[gw + 1];
    float ax = 0.f, ay = 0.f;
#pragma unroll 4
    for (int e = beg; e < end; e++) {
        int s = __ldg(&adj[e]);
        __half2 hv = __ldg(((const __half2*)(Yh + (size_t)s * HDIM)) + lane);
        float2 v = __half22float2(hv);
        ax += v.x; ay += v.y;
    }
    float inv = 1.f / (float)max(end - beg, 1);
    float2 z = __ldg(((const float2*)(Z + (size_t)gw * HDIM)) + lane);
    float ox = ax * inv + z.x;
    float oy = ay * inv + z.y;
    if (relu) { ox = fmaxf(ox, 0.f); oy = fmaxf(oy, 0.f); }
    ((float2*)(out + (size_t)gw * HDIM))[lane] = make_float2(ox, oy);
}

// ---------------- pos: out = tanh(pos @ W_pos + b), warp-per-node -----------
__global__ __launch_bounds__(256)
void pos_kernel(const float* __restrict__ pos, const float* __restrict__ W,
                const float* __restrict__ b, float* __restrict__ out, int N) {
    __shared__ float Ws[16 * 64];
    __shared__ float bs[64];
    int tid = threadIdx.x;
    for (int i = tid; i < 16 * 64; i += 256) Ws[i] = W[i];
    if (tid < 64) bs[tid] = b[tid];
    __syncthreads();

    int warp = tid >> 5, lane = tid & 31;
    int n = blockIdx.x * 8 + warp;
    if (n >= N) return;

    float pval = (lane < 16) ? __ldg(&pos[(size_t)n * 16 + lane]) : 0.f;
    int j0 = lane * 2;
    float a0 = bs[j0], a1 = bs[j0 + 1];
#pragma unroll
    for (int k = 0; k < 16; k++) {
        float pv = __shfl_sync(0xffffffffu, pval, k);
        float2 w = *(const float2*)&Ws[k * 64 + j0];
        a0 += pv * w.x; a1 += pv * w.y;
    }
    ((float2*)(out + (size_t)n * 64))[lane] = make_float2(tanhf(a0), tanhf(a1));
}

// ---------------- init GEMM: out[N,64] = A@W + b; A:[N,128] -----------------
__global__ void gemm_n64(const float* __restrict__ A0, int K0,
                         const float* __restrict__ W0,
                         const float* __restrict__ bias,
                         float* __restrict__ out, int N, int act) {
    __shared__ float As[128 * 68];
    const int node0 = blockIdx.x * 64;
    const int tid = threadIdx.x;
    const int K = K0;

    for (int i = tid; i < 64 * K; i += 256) {
        int nl = i / K, k = i - nl * K;
        int n = node0 + nl;
        float v = 0.f;
        if (n < N) v = A0[(size_t)n * K0 + k];
        As[k * 68 + nl] = v;
    }
    __syncthreads();

    const int fr = tid & 15;
    const int nr = tid >> 4;
    float acc[4][4];
#pragma unroll
    for (int i = 0; i < 4; i++)
#pragma unroll
        for (int j = 0; j < 4; j++) acc[i][j] = 0.f;

#pragma unroll 4
    for (int k = 0; k < K; k++) {
        float4 av = *(const float4*)&As[k * 68 + nr * 4];
        float4 wv = __ldg((const float4*)&W0[(size_t)k * 64 + fr * 4]);
        float a[4] = {av.x, av.y, av.z, av.w};
        float w[4] = {wv.x, wv.y, wv.z, wv.w};
#pragma unroll
        for (int i = 0; i < 4; i++)
#pragma unroll
            for (int j = 0; j < 4; j++) acc[i][j] += a[i] * w[j];
    }

    float b0 = bias[fr * 4 + 0], b1 = bias[fr * 4 + 1];
    float b2 = bias[fr * 4 + 2], b3 = bias[fr * 4 + 3];
#pragma unroll
    for (int i = 0; i < 4; i++) {
        int n = node0 + nr * 4 + i;
        if (n < N) {
            float4 v;
            v.x = acc[i][0] + b0; v.y = acc[i][1] + b1;
            v.z = acc[i][2] + b2; v.w = acc[i][3] + b3;
            if (act == 2) {
                v.x = tanhf(v.x); v.y = tanhf(v.y);
                v.z = tanhf(v.z); v.w = tanhf(v.w);
            }
            *(float4*)&out[(size_t)n * 64 + fr * 4] = v;
        }
    }
}

// ---------------- final: emb = h@W_last + b; log_softmax -----------------
__global__ void final_kernel(const float* __restrict__ h, const float* __restrict__ W,
                             const float* __restrict__ b, float* __restrict__ out,
                             int N, int out_size) {
    __shared__ float Ws[64 * 40];
    __shared__ float bs[40];
    int tid = threadIdx.x;
    for (int i = tid; i < 64 * 40; i += 256) Ws[i] = W[i];
    if (tid < 40) bs[tid] = b[tid];
    __syncthreads();

    int n = blockIdx.x * 256 + tid;
    if (n >= N) return;

    float acc[40];
#pragma unroll
    for (int c = 0; c < 40; c++) acc[c] = bs[c];
    const float* hr = h + (size_t)n * 64;
#pragma unroll 4
    for (int k = 0; k < 64; k++) {
        float hv = __ldg(&hr[k]);
#pragma unroll
        for (int c = 0; c < 40; c++) acc[c] += hv * Ws[k * 40 + c];
    }
    float mx = acc[0];
#pragma unroll
    for (int c = 1; c < 40; c++) mx = fmaxf(mx, acc[c]);
    float sum = 0.f;
#pragma unroll
    for (int c = 0; c < 40; c++) sum += expf(acc[c] - mx);
    float lse = mx + logf(sum);

    size_t base = (size_t)n * 40;
    size_t base2 = (size_t)N * 40 + base;
#pragma unroll
    for (int c = 0; c < 40; c++) {
        if (base + c < (size_t)out_size) out[base + c] = acc[c];
        if (base2 + c < (size_t)out_size) out[base2 + c] = acc[c] - lse;
    }
}

// ---------------- launch ----------------
extern "C" void kernel_launch(void* const* d_in, const int* in_sizes, int n_in,
                              void* d_out, int out_size) {
    const float* x_h    = (const float*)d_in[0];
    const float* pos    = (const float*)d_in[1];
    const int*   ei     = (const int*)  d_in[2];
    const float* W_pos  = (const float*)d_in[3];
    const float* b_pos  = (const float*)d_in[4];
    const float* W_init = (const float*)d_in[5];
    const float* b_init = (const float*)d_in[6];
    const float* W_l    = (const float*)d_in[7];
    const float* W_r    = (const float*)d_in[8];
    const float* b_conv = (const float*)d_in[9];
    const float* W_last = (const float*)d_in[10];
    const float* b_last = (const float*)d_in[11];

    int N = in_sizes[0] / 128;
    int E = in_sizes[2] / 2;

    float *hyp, *h0, *h1, *zbuf;
    __half* ybuf;
    int *rowptr, *cnt, *epos, *adj;
    cudaGetSymbolAddress((void**)&hyp,    g_hyp);
    cudaGetSymbolAddress((void**)&h0,     g_h0);
    cudaGetSymbolAddress((void**)&h1,     g_h1);
    cudaGetSymbolAddress((void**)&ybuf,   g_yh);
    cudaGetSymbolAddress((void**)&zbuf,   g_z);
    cudaGetSymbolAddress((void**)&rowptr, g_rowptr);
    cudaGetSymbolAddress((void**)&cnt,    g_cnt);
    cudaGetSymbolAddress((void**)&epos,   g_epos);
    cudaGetSymbolAddress((void**)&adj,    g_adj);

    const int* src = ei;
    const int* dst = ei + E;

    // host-side resources, created once; identical launch sequence every call
    static cudaStream_t s1 = nullptr;
    static cudaEvent_t ev_fork = nullptr, ev_join = nullptr;
    if (!s1) {
        cudaStreamCreateWithFlags(&s1, cudaStreamNonBlocking);
        cudaEventCreateWithFlags(&ev_fork, cudaEventDisableTiming);
        cudaEventCreateWithFlags(&ev_join, cudaEventDisableTiming);
    }

    // ---- fork: CSR build on s1, dense pipeline on default stream ----
    cudaEventRecord(ev_fork, 0);
    cudaStreamWaitEvent(s1, ev_fork, 0);

    cudaMemsetAsync(cnt, 0, (size_t)NMAX * sizeof(int), s1);
    count_kernel<<<(E + 255) / 256, 256, 0, s1>>>(dst, cnt, epos, E);
    scan_kernel <<<1, 1024, 0, s1>>>(cnt, rowptr, N);
    fill_kernel <<<(E + 255) / 256, 256, 0, s1>>>(src, dst, rowptr, epos, adj, E);
    cudaEventRecord(ev_join, s1);

    int gb64 = (N + 63) / 64;
    dim3 dual_grid(gb64, 2);
    // hyp = tanh(pos @ W_pos + b_pos)
    pos_kernel<<<(N + 7) / 8, 256>>>(pos, W_pos, b_pos, hyp, N);
    // h0 = x_h @ W_init + b_init
    gemm_n64<<<gb64, 256>>>(x_h, 128, W_init, b_init, h0, N, 0);
    // layer 0 dual GEMM (Y and Z as independent blocks)
    gemm_dual_split<<<dual_grid, 128>>>(h0, W_l, W_r, b_conv, hyp, ybuf, zbuf, N);

    // ---- join: CSR must be ready before first aggregation ----
    cudaStreamWaitEvent(0, ev_join, 0);

    agg_epi<<<(N + 7) / 8, 256>>>(ybuf, zbuf, h1, rowptr, adj, N, 1);

    float* hc = h1;
    float* hn = h0;
    for (int l = 1; l < 3; l++) {
        const float* Wl = W_l + (size_t)l * 64 * 64;
        const float* Wr = W_r + (size_t)l * 64 * 64;
        const float* bc = b_conv + (size_t)l * 64;
        const float* av = (l < 2) ? hyp : nullptr;
        int act = (l < 2) ? 1 : 0;
        gemm_dual_split<<<dual_grid, 128>>>(hc, Wl, Wr, bc, av, ybuf, zbuf, N);
        agg_epi<<<(N + 7) / 8, 256>>>(ybuf, zbuf, hn, rowptr, adj, N, act);
        float* t = hc; hc = hn; hn = t;
    }

    final_kernel<<<(N + 255) / 256, 256>>>(hc, W_last, b_last, (float*)d_out, N, out_size);
}